// round 1
// baseline (speedup 1.0000x reference)
#include <cuda_runtime.h>
#include <math.h>
#include <stdint.h>

#define E      1024
#define INNER  2048
#define NHQ    512
#define NH     4
#define DH     512
#define CK     4
#define S      46
#define B      64
#define OUT    512
#define NB     8
#define BS     (B*S)

// ---------------- static scratch (no allocations allowed) ----------------
__device__ float d_x[BS * E];              // residual stream
__device__ float d_xln[BS * E];            // LN(x)
__device__ float d_up[BS * 2 * INNER];     // [x_in | z]
__device__ float d_xact[BS * INNER];       // silu(conv(x_in))
__device__ float d_gatein[BS * 3 * INNER]; // [q | k | v]
__device__ float d_ipre[B * NH * S];
__device__ float d_fpre[B * NH * S];
__device__ float d_cum[B * NH * S];
__device__ float d_h[BS * INNER];          // mlstm out -> gated h
__device__ float d_last[B * E];            // final LN of last token

// ---------------- LayerNorm (rows of E) ----------------
__global__ __launch_bounds__(256) void ln_kernel(
    const float* __restrict__ in, size_t in_stride,
    const float* __restrict__ w,
    float* __restrict__ out, size_t out_stride)
{
    int row = blockIdx.x;
    const float* x = in + (size_t)row * in_stride;
    int tid = threadIdx.x;
    float s = 0.f, ss = 0.f;
    for (int i = tid; i < E; i += 256) { float v = x[i]; s += v; ss += v * v; }
    __shared__ float r1[256], r2[256];
    r1[tid] = s; r2[tid] = ss;
    __syncthreads();
    for (int st = 128; st > 0; st >>= 1) {
        if (tid < st) { r1[tid] += r1[tid + st]; r2[tid] += r2[tid + st]; }
        __syncthreads();
    }
    float mean = r1[0] * (1.f / E);
    float var  = r2[0] * (1.f / E) - mean * mean;
    float inv  = rsqrtf(var + 1e-5f);
    float* o = out + (size_t)row * out_stride;
    for (int i = tid; i < E; i += 256) o[i] = (x[i] - mean) * inv * w[i];
}

// ---------------- 128x128x8 tiled SGEMM, optional C += ----------------
// M,N,K all multiples of 128/128/8 here (M=2944, N in {4096,1024}, K in {1024,2048})
template<int ADD>
__global__ __launch_bounds__(256) void sgemm_kernel(
    const float* __restrict__ A, const float* __restrict__ Bm,
    float* __restrict__ C, int M, int N, int Kd)
{
    __shared__ float As[8][128];
    __shared__ float Bs[8][128];
    int tid = threadIdx.x;
    int bm = blockIdx.y * 128, bn = blockIdx.x * 128;

    int aRow = tid >> 1, aCol = (tid & 1) * 4;
    int bRow = tid >> 5, bCol = (tid & 31) * 4;
    const float* Aptr = A + (size_t)(bm + aRow) * Kd + aCol;
    const float* Bptr = Bm + (size_t)bRow * N + bn + bCol;

    int tr = (tid >> 4) * 8, tc = (tid & 15) * 8;
    float acc[8][8] = {};

    for (int k0 = 0; k0 < Kd; k0 += 8) {
        float4 av = *(const float4*)Aptr; Aptr += 8;
        float4 bv = *(const float4*)Bptr; Bptr += (size_t)8 * N;
        As[aCol + 0][aRow] = av.x; As[aCol + 1][aRow] = av.y;
        As[aCol + 2][aRow] = av.z; As[aCol + 3][aRow] = av.w;
        *(float4*)&Bs[bRow][bCol] = bv;
        __syncthreads();
        #pragma unroll
        for (int kk = 0; kk < 8; kk++) {
            float ra[8], rb[8];
            #pragma unroll
            for (int i = 0; i < 8; i++) ra[i] = As[kk][tr + i];
            #pragma unroll
            for (int j = 0; j < 8; j++) rb[j] = Bs[kk][tc + j];
            #pragma unroll
            for (int i = 0; i < 8; i++)
                #pragma unroll
                for (int j = 0; j < 8; j++)
                    acc[i][j] += ra[i] * rb[j];
        }
        __syncthreads();
    }
    #pragma unroll
    for (int i = 0; i < 8; i++) {
        float* crow = C + (size_t)(bm + tr + i) * N + bn + tc;
        #pragma unroll
        for (int j = 0; j < 8; j++) {
            float v = acc[i][j];
            if (ADD) v += crow[j];
            crow[j] = v;
        }
    }
}

// ---------------- causal depthwise conv (K=4) + SiLU ----------------
__global__ __launch_bounds__(256) void conv_silu_kernel(
    const float* __restrict__ cw, const float* __restrict__ cb)
{
    int c = blockIdx.x * 256 + threadIdx.x;   // channel
    int b = blockIdx.y;
    float w0 = cw[c * CK + 0], w1 = cw[c * CK + 1];
    float w2 = cw[c * CK + 2], w3 = cw[c * CK + 3];
    float bias = cb[c];
    const float* src = d_up + (size_t)b * S * 2 * INNER + c;
    float* dst = d_xact + (size_t)b * S * INNER + c;
    float x0 = 0.f, x1 = 0.f, x2 = 0.f;
    for (int s = 0; s < S; s++) {
        float x3 = src[(size_t)s * 2 * INNER];
        float o = w0 * x0 + w1 * x1 + w2 * x2 + w3 * x3 + bias;
        dst[(size_t)s * INNER] = o / (1.f + expf(-o));  // silu
        x0 = x1; x1 = x2; x2 = x3;
    }
}

// ---------------- headwise 4x4 q/k/v -> gate_in [q|k|v] ----------------
__global__ void headwise_kernel(
    const float* __restrict__ wq, const float* __restrict__ wk,
    const float* __restrict__ wv)
{
    int idx = blockIdx.x * blockDim.x + threadIdx.x;
    if (idx >= BS * NHQ) return;
    int hq = idx & (NHQ - 1);
    int row = idx >> 9;
    float a[4], xi[4];
    *(float4*)a  = *(const float4*)(d_xact + (size_t)row * INNER + hq * 4);
    *(float4*)xi = *(const float4*)(d_up + (size_t)row * 2 * INNER + hq * 4);
    const float* Wq = wq + hq * 16;
    const float* Wk = wk + hq * 16;
    const float* Wv = wv + hq * 16;
    float qo[4], ko[4], vo[4];
    #pragma unroll
    for (int o = 0; o < 4; o++) {
        float sq = 0.f, sk = 0.f, sv = 0.f;
        #pragma unroll
        for (int d = 0; d < 4; d++) {
            sq += Wq[o * 4 + d] * a[d];
            sk += Wk[o * 4 + d] * a[d];
            sv += Wv[o * 4 + d] * xi[d];
        }
        qo[o] = sq; ko[o] = sk; vo[o] = sv;
    }
    float* g = d_gatein + (size_t)row * 3 * INNER;
    *(float4*)(g + hq * 4)              = *(float4*)qo;
    *(float4*)(g + INNER + hq * 4)      = *(float4*)ko;
    *(float4*)(g + 2 * INNER + hq * 4)  = *(float4*)vo;
}

// ---------------- gate pre-activations (8 dots of 6144 per row) ----------------
__global__ __launch_bounds__(256) void gate_kernel(
    const float* __restrict__ igw, const float* __restrict__ igb,
    const float* __restrict__ fgw, const float* __restrict__ fgb)
{
    int row = blockIdx.x;                 // b*S + s
    int b = row / S, s = row - b * S;
    int tid = threadIdx.x;
    const float* g = d_gatein + (size_t)row * 3 * INNER;
    float acc[8] = {0.f,0.f,0.f,0.f,0.f,0.f,0.f,0.f};
    for (int r = tid; r < 3 * INNER; r += 256) {
        float gv = g[r];
        const float* iw = igw + (size_t)r * NH;
        const float* fw = fgw + (size_t)r * NH;
        acc[0] += gv * iw[0]; acc[1] += gv * iw[1];
        acc[2] += gv * iw[2]; acc[3] += gv * iw[3];
        acc[4] += gv * fw[0]; acc[5] += gv * fw[1];
        acc[6] += gv * fw[2]; acc[7] += gv * fw[3];
    }
    __shared__ float red[8][256];
    #pragma unroll
    for (int h = 0; h < 8; h++) red[h][tid] = acc[h];
    __syncthreads();
    for (int st = 128; st > 0; st >>= 1) {
        if (tid < st) {
            #pragma unroll
            for (int h = 0; h < 8; h++) red[h][tid] += red[h][tid + st];
        }
        __syncthreads();
    }
    if (tid < 4)
        d_ipre[(b * NH + tid) * S + s] = red[tid][0] + igb[tid];
    else if (tid < 8)
        d_fpre[(b * NH + (tid - 4)) * S + s] = red[tid][0] + fgb[tid - 4];
}

// ---------------- cumsum of log-sigmoid(fpre) ----------------
__global__ void cumsum_kernel()
{
    int i = blockIdx.x * blockDim.x + threadIdx.x;
    if (i >= B * NH) return;
    const float* f = d_fpre + (size_t)i * S;
    float* c = d_cum + (size_t)i * S;
    float acc = 0.f;
    for (int s = 0; s < S; s++) {
        float x = f[s];
        float ls = (x < 0.f) ? (x - log1pf(expf(x))) : (-log1pf(expf(-x)));
        acc += ls;
        c[s] = acc;
    }
}

// ---------------- mLSTM: one block per (b, h, t) ----------------
__global__ __launch_bounds__(256) void mlstm_kernel()
{
    int t  = blockIdx.x;       // 0..S-1
    int bh = blockIdx.y;       // 0..B*NH-1
    int b = bh / NH, hh = bh - b * NH;
    int tid = threadIdx.x;
    int warp = tid >> 5, lane = tid & 31;

    __shared__ float qs[DH];
    __shared__ float cums[S], ips[S];
    __shared__ float coeff[S];

    const float* gbase = d_gatein + (size_t)b * S * 3 * INNER;
    const float* qrow = gbase + (size_t)t * 3 * INNER + hh * DH;
    for (int i = tid; i < DH; i += 256) qs[i] = qrow[i];
    if (tid < S) { cums[tid] = d_cum[bh * S + tid]; ips[tid] = d_ipre[bh * S + tid]; }
    __syncthreads();

    int nvalid = t + 1;
    // warp-per-s raw dot products q[t]·k[s]
    for (int s = warp; s < nvalid; s += 8) {
        const float* krow = gbase + (size_t)s * 3 * INNER + INNER + hh * DH;
        float p = 0.f;
        for (int j = lane; j < DH; j += 32) p += qs[j] * krow[j];
        #pragma unroll
        for (int off = 16; off; off >>= 1) p += __shfl_down_sync(0xffffffffu, p, off);
        if (lane == 0) coeff[s] = p;
    }
    __syncthreads();

    if (tid == 0) {
        float ct = cums[t];
        float m = -INFINITY;
        for (int s = 0; s < nvalid; s++) {
            float ld = ct - cums[s] + ips[s];
            if (ld > m) m = ld;
        }
        const float scale = rsqrtf((float)DH);
        float csum = 0.f;
        for (int s = 0; s < nvalid; s++) {
            float ld = ct - cums[s] + ips[s];
            float cv = coeff[s] * scale * expf(ld - m);
            coeff[s] = cv;
            csum += cv;
        }
        float denom = fmaxf(fabsf(csum), expf(-m)) + 1e-6f;
        float inv = 1.f / denom;
        for (int s = 0; s < nvalid; s++) coeff[s] *= inv;
    }
    __syncthreads();

    float acc0 = 0.f, acc1 = 0.f;
    int d0 = tid, d1 = tid + 256;
    for (int s = 0; s < nvalid; s++) {
        const float* vrow = gbase + (size_t)s * 3 * INNER + 2 * INNER + hh * DH;
        float cs = coeff[s];
        acc0 += cs * vrow[d0];
        acc1 += cs * vrow[d1];
    }
    float* hrow = d_h + (size_t)(b * S + t) * INNER + hh * DH;
    hrow[d0] = acc0;
    hrow[d1] = acc1;
}

// ---------------- per-head norm + skip + z-gating (in place on d_h) ----------------
__global__ __launch_bounds__(256) void mhnorm_kernel(
    const float* __restrict__ mhw, const float* __restrict__ skipw)
{
    int row = blockIdx.x;   // b*S + s
    int hh  = blockIdx.y;   // head
    int tid = threadIdx.x;
    float* hp = d_h + (size_t)row * INNER + (size_t)hh * DH;
    float v0 = hp[tid], v1 = hp[tid + 256];
    __shared__ float r1[256], r2[256];
    r1[tid] = v0 + v1;
    r2[tid] = v0 * v0 + v1 * v1;
    __syncthreads();
    for (int st = 128; st > 0; st >>= 1) {
        if (tid < st) { r1[tid] += r1[tid + st]; r2[tid] += r2[tid + st]; }
        __syncthreads();
    }
    float mean = r1[0] * (1.f / DH);
    float var  = r2[0] * (1.f / DH) - mean * mean;
    float inv  = rsqrtf(var + 1e-5f);
    #pragma unroll
    for (int p = 0; p < 2; p++) {
        int i = tid + p * 256;
        int c = hh * DH + i;
        float z  = d_up[(size_t)row * 2 * INNER + INNER + c];
        float sz = z / (1.f + expf(-z));
        float hv = p ? v1 : v0;
        float val = (hv - mean) * inv * mhw[c] + skipw[c] * d_xact[(size_t)row * INNER + c];
        hp[i] = val * sz;
    }
}

// ---------------- final projection ----------------
__global__ void proj_kernel(const float* __restrict__ pw,
                            const float* __restrict__ pb,
                            float* __restrict__ out)
{
    int o = blockIdx.x * blockDim.x + threadIdx.x;   // 0..OUT-1
    int b = blockIdx.y;
    const float* l = d_last + (size_t)b * E;
    float acc = pb[o];
    for (int e = 0; e < E; e++) acc += l[e] * pw[(size_t)e * OUT + o];
    out[b * OUT + o] = acc;
}

// ---------------- host launcher ----------------
extern "C" void kernel_launch(void* const* d_in, const int* in_sizes, int n_in,
                              void* d_out, int out_size)
{
    const float* in_x      = (const float*)d_in[0];
    const float* ln_w      = (const float*)d_in[1];
    const float* w_up      = (const float*)d_in[2];
    const float* conv_w    = (const float*)d_in[3];
    const float* conv_b    = (const float*)d_in[4];
    const float* wq        = (const float*)d_in[5];
    const float* wk        = (const float*)d_in[6];
    const float* wv        = (const float*)d_in[7];
    const float* ig_w      = (const float*)d_in[8];
    const float* ig_b      = (const float*)d_in[9];
    const float* fg_w      = (const float*)d_in[10];
    const float* fg_b      = (const float*)d_in[11];
    const float* skip      = (const float*)d_in[12];
    const float* mhn_w     = (const float*)d_in[13];
    const float* w_down    = (const float*)d_in[14];
    const float* post_ln_w = (const float*)d_in[15];
    const float* proj_w    = (const float*)d_in[16];
    const float* proj_b    = (const float*)d_in[17];
    float* out = (float*)d_out;

    float *px, *pxln, *pup, *ph, *plast;
    cudaGetSymbolAddress((void**)&px,    d_x);
    cudaGetSymbolAddress((void**)&pxln,  d_xln);
    cudaGetSymbolAddress((void**)&pup,   d_up);
    cudaGetSymbolAddress((void**)&ph,    d_h);
    cudaGetSymbolAddress((void**)&plast, d_last);

    cudaMemcpyAsync(px, in_x, sizeof(float) * (size_t)BS * E,
                    cudaMemcpyDeviceToDevice);

    for (int bi = 0; bi < NB; bi++) {
        ln_kernel<<<BS, 256>>>(px, E, ln_w + (size_t)bi * E, pxln, E);

        dim3 gu(2 * INNER / 128, BS / 128);
        sgemm_kernel<0><<<gu, 256>>>(pxln, w_up + (size_t)bi * E * 2 * INNER,
                                     pup, BS, 2 * INNER, E);

        conv_silu_kernel<<<dim3(INNER / 256, B), 256>>>(
            conv_w + (size_t)bi * INNER * CK, conv_b + (size_t)bi * INNER);

        headwise_kernel<<<(BS * NHQ + 255) / 256, 256>>>(
            wq + (size_t)bi * NHQ * 16, wk + (size_t)bi * NHQ * 16,
            wv + (size_t)bi * NHQ * 16);

        gate_kernel<<<BS, 256>>>(
            ig_w + (size_t)bi * 3 * INNER * NH, ig_b + (size_t)bi * NH,
            fg_w + (size_t)bi * 3 * INNER * NH, fg_b + (size_t)bi * NH);

        cumsum_kernel<<<1, 256>>>();

        mlstm_kernel<<<dim3(S, B * NH), 256>>>();

        mhnorm_kernel<<<dim3(BS, NH), 256>>>(
            mhn_w + (size_t)bi * INNER, skip + (size_t)bi * INNER);

        dim3 gd(E / 128, BS / 128);
        sgemm_kernel<1><<<gd, 256>>>(ph, w_down + (size_t)bi * INNER * E,
                                     px, BS, E, INNER);
    }

    ln_kernel<<<B, 256>>>(px + (size_t)(S - 1) * E, (size_t)S * E,
                          post_ln_w, plast, E);
    proj_kernel<<<dim3(OUT / 256, B), 256>>>(proj_w, proj_b, out);
}

// round 2
// speedup vs baseline: 2.2333x; 2.2333x over previous
#include <cuda_runtime.h>
#include <cuda_bf16.h>
#include <math.h>
#include <stdint.h>

#define E      1024
#define INNER  2048
#define NHQ    512
#define NH     4
#define DH     512
#define CK     4
#define S      46
#define B      64
#define OUT    512
#define NB     8
#define BS     (B*S)

// ---------------- static scratch (no allocations allowed) ----------------
__device__ float d_x[BS * E];              // residual stream
__device__ float d_up[BS * 2 * INNER];     // [x_in | z]
__device__ float d_xact[BS * INNER];       // silu(conv(x_in))
__device__ float d_gatein[BS * 3 * INNER]; // [q | k | v]
__device__ float d_ipre[B * NH * S];
__device__ float d_fpre[B * NH * S];
__device__ float d_cum[B * NH * S];
__device__ float d_h[BS * INNER];          // raw mlstm out
__device__ float d_last[B * E];            // final LN of last token

// split-bf16 operands
__device__ __nv_bfloat16 d_xlnhi[BS * E];
__device__ __nv_bfloat16 d_xlnlo[BS * E];
__device__ __nv_bfloat16 d_hhi[BS * INNER];
__device__ __nv_bfloat16 d_hlo[BS * INNER];
__device__ __nv_bfloat16 d_wuphi[NB * E * 2 * INNER];
__device__ __nv_bfloat16 d_wuplo[NB * E * 2 * INNER];
__device__ __nv_bfloat16 d_wdnhi[NB * INNER * E];
__device__ __nv_bfloat16 d_wdnlo[NB * INNER * E];

// ---------------- helpers ----------------
__device__ __forceinline__ uint32_t smem_u32(const void* p) {
    return (uint32_t)__cvta_generic_to_shared(p);
}
__device__ __forceinline__ void ldsm4(uint32_t& r0, uint32_t& r1, uint32_t& r2, uint32_t& r3, uint32_t addr) {
    asm volatile("ldmatrix.sync.aligned.m8n8.x4.shared.b16 {%0,%1,%2,%3}, [%4];"
                 : "=r"(r0), "=r"(r1), "=r"(r2), "=r"(r3) : "r"(addr));
}
__device__ __forceinline__ void ldsm4t(uint32_t& r0, uint32_t& r1, uint32_t& r2, uint32_t& r3, uint32_t addr) {
    asm volatile("ldmatrix.sync.aligned.m8n8.x4.trans.shared.b16 {%0,%1,%2,%3}, [%4];"
                 : "=r"(r0), "=r"(r1), "=r"(r2), "=r"(r3) : "r"(addr));
}
__device__ __forceinline__ void mma16816(float* d, const uint32_t* a, const uint32_t* b) {
    asm volatile("mma.sync.aligned.m16n8k16.row.col.f32.bf16.bf16.f32 "
                 "{%0,%1,%2,%3}, {%4,%5,%6,%7}, {%8,%9}, {%0,%1,%2,%3};"
                 : "+f"(d[0]), "+f"(d[1]), "+f"(d[2]), "+f"(d[3])
                 : "r"(a[0]), "r"(a[1]), "r"(a[2]), "r"(a[3]), "r"(b[0]), "r"(b[1]));
}
__device__ __forceinline__ void split1(float x, __nv_bfloat16& h, __nv_bfloat16& l) {
    h = __float2bfloat16_rn(x);
    l = __float2bfloat16_rn(x - __bfloat162float(h));
}

// ---------------- fp32 -> (hi,lo) bf16 split ----------------
__global__ __launch_bounds__(256) void split_kernel(
    const float* __restrict__ src, __nv_bfloat16* __restrict__ hi,
    __nv_bfloat16* __restrict__ lo, size_t n)
{
    size_t i = ((size_t)blockIdx.x * 256 + threadIdx.x) * 4;
    if (i >= n) return;
    float4 v = *(const float4*)(src + i);
    __nv_bfloat16 h0, h1, h2, h3, l0, l1, l2, l3;
    split1(v.x, h0, l0); split1(v.y, h1, l1);
    split1(v.z, h2, l2); split1(v.w, h3, l3);
    *(__nv_bfloat162*)(hi + i)     = __nv_bfloat162(h0, h1);
    *(__nv_bfloat162*)(hi + i + 2) = __nv_bfloat162(h2, h3);
    *(__nv_bfloat162*)(lo + i)     = __nv_bfloat162(l0, l1);
    *(__nv_bfloat162*)(lo + i + 2) = __nv_bfloat162(l2, l3);
}

// ---------------- LayerNorm (rows of E), optional split output ----------------
template<int SPLIT>
__global__ __launch_bounds__(256) void ln_kernel(
    const float* __restrict__ in, size_t in_stride,
    const float* __restrict__ w,
    float* __restrict__ outf,
    __nv_bfloat16* __restrict__ oh, __nv_bfloat16* __restrict__ ol,
    size_t out_stride)
{
    int row = blockIdx.x;
    const float* x = in + (size_t)row * in_stride;
    int tid = threadIdx.x;
    float s = 0.f, ss = 0.f;
    for (int i = tid; i < E; i += 256) { float v = x[i]; s += v; ss += v * v; }
    __shared__ float r1[256], r2[256];
    r1[tid] = s; r2[tid] = ss;
    __syncthreads();
    for (int st = 128; st > 0; st >>= 1) {
        if (tid < st) { r1[tid] += r1[tid + st]; r2[tid] += r2[tid + st]; }
        __syncthreads();
    }
    float mean = r1[0] * (1.f / E);
    float var  = r2[0] * (1.f / E) - mean * mean;
    float inv  = rsqrtf(var + 1e-5f);
    for (int i = tid; i < E; i += 256) {
        float v = (x[i] - mean) * inv * w[i];
        if (SPLIT) {
            __nv_bfloat16 h, l;
            split1(v, h, l);
            oh[(size_t)row * out_stride + i] = h;
            ol[(size_t)row * out_stride + i] = l;
        } else {
            outf[(size_t)row * out_stride + i] = v;
        }
    }
}

// ---------------- split-bf16 128x128x32 GEMM (3-term), optional C += ----------------
template<int ADD>
__global__ __launch_bounds__(256) void gemm_kernel(
    const __nv_bfloat16* __restrict__ Ahg, const __nv_bfloat16* __restrict__ Alg,
    const __nv_bfloat16* __restrict__ Bhg, const __nv_bfloat16* __restrict__ Blg,
    float* __restrict__ C, int M, int N, int Kd)
{
    __shared__ __nv_bfloat16 sAh[128][40], sAl[128][40];
    __shared__ __nv_bfloat16 sBh[32][136], sBl[32][136];

    int tid  = threadIdx.x;
    int lane = tid & 31, warp = tid >> 5;
    int bm = blockIdx.y * 128, bn = blockIdx.x * 128;
    int wm = (warp >> 1) * 32;     // warp row offset within tile
    int wn = (warp & 1) * 64;      // warp col offset within tile

    // tile-load geometry (vec8 = uint4 of 8 bf16)
    int ar0 = tid >> 2,          ac0 = (tid & 3) * 8;
    int ar1 = (tid + 256) >> 2,  ac1 = (tid & 3) * 8;
    int br0 = tid >> 4,          bc0 = (tid & 15) * 8;
    int br1 = (tid + 256) >> 4,  bc1 = (tid & 15) * 8;

    size_t aoff0 = (size_t)(bm + ar0) * Kd + ac0;
    size_t aoff1 = (size_t)(bm + ar1) * Kd + ac1;
    size_t boff0 = (size_t)br0 * N + bn + bc0;
    size_t boff1 = (size_t)br1 * N + bn + bc1;

    // ldmatrix lane bases
    int a_row = lane & 15, a_col = (lane >> 4) * 8;
    int b_row = (lane & 7) + ((lane >> 3) & 1) * 8;
    int b_col = (lane >> 4) * 8;

    float acc[2][8][4];
    #pragma unroll
    for (int i = 0; i < 2; i++)
        #pragma unroll
        for (int j = 0; j < 8; j++)
            #pragma unroll
            for (int q = 0; q < 4; q++) acc[i][j][q] = 0.f;

    int ntiles = Kd >> 5;
    uint4 pAh0 = *(const uint4*)(Ahg + aoff0);
    uint4 pAh1 = *(const uint4*)(Ahg + aoff1);
    uint4 pAl0 = *(const uint4*)(Alg + aoff0);
    uint4 pAl1 = *(const uint4*)(Alg + aoff1);
    uint4 pBh0 = *(const uint4*)(Bhg + boff0);
    uint4 pBh1 = *(const uint4*)(Bhg + boff1);
    uint4 pBl0 = *(const uint4*)(Blg + boff0);
    uint4 pBl1 = *(const uint4*)(Blg + boff1);

    for (int kt = 0; kt < ntiles; kt++) {
        *(uint4*)&sAh[ar0][ac0] = pAh0;
        *(uint4*)&sAh[ar1][ac1] = pAh1;
        *(uint4*)&sAl[ar0][ac0] = pAl0;
        *(uint4*)&sAl[ar1][ac1] = pAl1;
        *(uint4*)&sBh[br0][bc0] = pBh0;
        *(uint4*)&sBh[br1][bc1] = pBh1;
        *(uint4*)&sBl[br0][bc0] = pBl0;
        *(uint4*)&sBl[br1][bc1] = pBl1;
        __syncthreads();

        if (kt + 1 < ntiles) {
            int k0 = (kt + 1) * 32;
            pAh0 = *(const uint4*)(Ahg + aoff0 + k0);
            pAh1 = *(const uint4*)(Ahg + aoff1 + k0);
            pAl0 = *(const uint4*)(Alg + aoff0 + k0);
            pAl1 = *(const uint4*)(Alg + aoff1 + k0);
            pBh0 = *(const uint4*)(Bhg + boff0 + (size_t)k0 * N);
            pBh1 = *(const uint4*)(Bhg + boff1 + (size_t)k0 * N);
            pBl0 = *(const uint4*)(Blg + boff0 + (size_t)k0 * N);
            pBl1 = *(const uint4*)(Blg + boff1 + (size_t)k0 * N);
        }

        #pragma unroll
        for (int h = 0; h < 2; h++) {
            uint32_t ah[2][4], al[2][4];
            #pragma unroll
            for (int mt = 0; mt < 2; mt++) {
                ldsm4(ah[mt][0], ah[mt][1], ah[mt][2], ah[mt][3],
                      smem_u32(&sAh[wm + mt * 16 + a_row][h * 16 + a_col]));
                ldsm4(al[mt][0], al[mt][1], al[mt][2], al[mt][3],
                      smem_u32(&sAl[wm + mt * 16 + a_row][h * 16 + a_col]));
            }
            #pragma unroll
            for (int ng = 0; ng < 4; ng++) {
                uint32_t bh[4], bl[4];
                ldsm4t(bh[0], bh[1], bh[2], bh[3],
                       smem_u32(&sBh[h * 16 + b_row][wn + ng * 16 + b_col]));
                ldsm4t(bl[0], bl[1], bl[2], bl[3],
                       smem_u32(&sBl[h * 16 + b_row][wn + ng * 16 + b_col]));
                #pragma unroll
                for (int mt = 0; mt < 2; mt++) {
                    #pragma unroll
                    for (int nn = 0; nn < 2; nn++) {
                        float* d = acc[mt][ng * 2 + nn];
                        mma16816(d, ah[mt], &bh[nn * 2]);
                        mma16816(d, ah[mt], &bl[nn * 2]);
                        mma16816(d, al[mt], &bh[nn * 2]);
                    }
                }
            }
        }
        __syncthreads();
    }

    // epilogue
    int g = lane >> 2, t2 = (lane & 3) * 2;
    #pragma unroll
    for (int mt = 0; mt < 2; mt++) {
        #pragma unroll
        for (int nt = 0; nt < 8; nt++) {
            int row = bm + wm + mt * 16 + g;
            int col = bn + wn + nt * 8 + t2;
            float* d = acc[mt][nt];
            float2* p0 = (float2*)&C[(size_t)row * N + col];
            float2* p1 = (float2*)&C[(size_t)(row + 8) * N + col];
            float2 v0 = make_float2(d[0], d[1]);
            float2 v1 = make_float2(d[2], d[3]);
            if (ADD) {
                float2 o0 = *p0, o1 = *p1;
                v0.x += o0.x; v0.y += o0.y;
                v1.x += o1.x; v1.y += o1.y;
            }
            *p0 = v0; *p1 = v1;
        }
    }
}

// ---------------- causal depthwise conv (K=4) + SiLU ----------------
__global__ __launch_bounds__(256) void conv_silu_kernel(
    const float* __restrict__ cw, const float* __restrict__ cb)
{
    int c = blockIdx.x * 256 + threadIdx.x;   // channel
    int b = blockIdx.y;
    float w0 = cw[c * CK + 0], w1 = cw[c * CK + 1];
    float w2 = cw[c * CK + 2], w3 = cw[c * CK + 3];
    float bias = cb[c];
    const float* src = d_up + (size_t)b * S * 2 * INNER + c;
    float* dst = d_xact + (size_t)b * S * INNER + c;
    float x0 = 0.f, x1 = 0.f, x2 = 0.f;
    for (int s = 0; s < S; s++) {
        float x3 = src[(size_t)s * 2 * INNER];
        float o = w0 * x0 + w1 * x1 + w2 * x2 + w3 * x3 + bias;
        dst[(size_t)s * INNER] = o / (1.f + expf(-o));  // silu
        x0 = x1; x1 = x2; x2 = x3;
    }
}

// ---------------- headwise 4x4 q/k/v -> gate_in [q|k|v] ----------------
// thread = one hq head; weights live in registers; 16 rows per block
__global__ __launch_bounds__(128) void headwise_kernel(
    const float* __restrict__ wq, const float* __restrict__ wk,
    const float* __restrict__ wv)
{
    int hq = blockIdx.x * 128 + threadIdx.x;
    int r0 = blockIdx.y * 16;
    float Wq[16], Wk[16], Wv[16];
    #pragma unroll
    for (int i = 0; i < 4; i++) {
        ((float4*)Wq)[i] = ((const float4*)(wq + hq * 16))[i];
        ((float4*)Wk)[i] = ((const float4*)(wk + hq * 16))[i];
        ((float4*)Wv)[i] = ((const float4*)(wv + hq * 16))[i];
    }
    #pragma unroll 4
    for (int r = 0; r < 16; r++) {
        int row = r0 + r;
        float a[4], xi[4];
        *(float4*)a  = *(const float4*)(d_xact + (size_t)row * INNER + hq * 4);
        *(float4*)xi = *(const float4*)(d_up + (size_t)row * 2 * INNER + hq * 4);
        float qo[4], ko[4], vo[4];
        #pragma unroll
        for (int o = 0; o < 4; o++) {
            float sq = 0.f, sk = 0.f, sv = 0.f;
            #pragma unroll
            for (int d = 0; d < 4; d++) {
                sq += Wq[o * 4 + d] * a[d];
                sk += Wk[o * 4 + d] * a[d];
                sv += Wv[o * 4 + d] * xi[d];
            }
            qo[o] = sq; ko[o] = sk; vo[o] = sv;
        }
        float* gp = d_gatein + (size_t)row * 3 * INNER;
        *(float4*)(gp + hq * 4)             = *(float4*)qo;
        *(float4*)(gp + INNER + hq * 4)     = *(float4*)ko;
        *(float4*)(gp + 2 * INNER + hq * 4) = *(float4*)vo;
    }
}

// ---------------- gate pre-activations (8 dots of 6144 per row) ----------------
__global__ __launch_bounds__(256) void gate_kernel(
    const float* __restrict__ igw, const float* __restrict__ igb,
    const float* __restrict__ fgw, const float* __restrict__ fgb)
{
    int row = blockIdx.x;                 // b*S + s
    int b = row / S, s = row - b * S;
    int tid = threadIdx.x;
    const float* g = d_gatein + (size_t)row * 3 * INNER;
    float acc[8] = {0.f,0.f,0.f,0.f,0.f,0.f,0.f,0.f};
    for (int r = tid; r < 3 * INNER; r += 256) {
        float gv = g[r];
        float4 iw = *(const float4*)(igw + (size_t)r * NH);
        float4 fw = *(const float4*)(fgw + (size_t)r * NH);
        acc[0] += gv * iw.x; acc[1] += gv * iw.y;
        acc[2] += gv * iw.z; acc[3] += gv * iw.w;
        acc[4] += gv * fw.x; acc[5] += gv * fw.y;
        acc[6] += gv * fw.z; acc[7] += gv * fw.w;
    }
    __shared__ float red[8][256];
    #pragma unroll
    for (int h = 0; h < 8; h++) red[h][tid] = acc[h];
    __syncthreads();
    for (int st = 128; st > 0; st >>= 1) {
        if (tid < st) {
            #pragma unroll
            for (int h = 0; h < 8; h++) red[h][tid] += red[h][tid + st];
        }
        __syncthreads();
    }
    if (tid < 4)
        d_ipre[(b * NH + tid) * S + s] = red[tid][0] + igb[tid];
    else if (tid < 8)
        d_fpre[(b * NH + (tid - 4)) * S + s] = red[tid][0] + fgb[tid - 4];
}

// ---------------- cumsum of log-sigmoid(fpre) ----------------
__global__ void cumsum_kernel()
{
    int i = blockIdx.x * blockDim.x + threadIdx.x;
    if (i >= B * NH) return;
    const float* f = d_fpre + (size_t)i * S;
    float* c = d_cum + (size_t)i * S;
    float acc = 0.f;
    for (int s = 0; s < S; s++) {
        float x = f[s];
        float ls = (x < 0.f) ? (x - log1pf(expf(x))) : (-log1pf(expf(-x)));
        acc += ls;
        c[s] = acc;
    }
}

// ---------------- mLSTM: one block per (b, h, t) ----------------
__global__ __launch_bounds__(256) void mlstm_kernel()
{
    int t  = blockIdx.x;       // 0..S-1
    int bh = blockIdx.y;       // 0..B*NH-1
    int b = bh / NH, hh = bh - b * NH;
    int tid = threadIdx.x;
    int warp = tid >> 5, lane = tid & 31;

    __shared__ float qs[DH];
    __shared__ float cums[S], ips[S];
    __shared__ float coeff[S];

    const float* gbase = d_gatein + (size_t)b * S * 3 * INNER;
    const float* qrow = gbase + (size_t)t * 3 * INNER + hh * DH;
    for (int i = tid; i < DH; i += 256) qs[i] = qrow[i];
    if (tid < S) { cums[tid] = d_cum[bh * S + tid]; ips[tid] = d_ipre[bh * S + tid]; }
    __syncthreads();

    int nvalid = t + 1;
    for (int s = warp; s < nvalid; s += 8) {
        const float* krow = gbase + (size_t)s * 3 * INNER + INNER + hh * DH;
        float p = 0.f;
        for (int j = lane; j < DH; j += 32) p += qs[j] * krow[j];
        #pragma unroll
        for (int off = 16; off; off >>= 1) p += __shfl_down_sync(0xffffffffu, p, off);
        if (lane == 0) coeff[s] = p;
    }
    __syncthreads();

    if (tid == 0) {
        float ct = cums[t];
        float m = -INFINITY;
        for (int s = 0; s < nvalid; s++) {
            float ld = ct - cums[s] + ips[s];
            if (ld > m) m = ld;
        }
        const float scale = rsqrtf((float)DH);
        float csum = 0.f;
        for (int s = 0; s < nvalid; s++) {
            float ld = ct - cums[s] + ips[s];
            float cv = coeff[s] * scale * expf(ld - m);
            coeff[s] = cv;
            csum += cv;
        }
        float denom = fmaxf(fabsf(csum), expf(-m)) + 1e-6f;
        float inv = 1.f / denom;
        for (int s = 0; s < nvalid; s++) coeff[s] *= inv;
    }
    __syncthreads();

    float acc0 = 0.f, acc1 = 0.f;
    int d0 = tid, d1 = tid + 256;
    for (int s = 0; s < nvalid; s++) {
        const float* vrow = gbase + (size_t)s * 3 * INNER + 2 * INNER + hh * DH;
        float cs = coeff[s];
        acc0 += cs * vrow[d0];
        acc1 += cs * vrow[d1];
    }
    float* hrow = d_h + (size_t)(b * S + t) * INNER + hh * DH;
    hrow[d0] = acc0;
    hrow[d1] = acc1;
}

// ---------------- per-head norm + skip + z-gating -> split bf16 h ----------------
__global__ __launch_bounds__(256) void mhnorm_kernel(
    const float* __restrict__ mhw, const float* __restrict__ skipw)
{
    int row = blockIdx.x;   // b*S + s
    int hh  = blockIdx.y;   // head
    int tid = threadIdx.x;
    const float* hp = d_h + (size_t)row * INNER + (size_t)hh * DH;
    float v0 = hp[tid], v1 = hp[tid + 256];
    __shared__ float r1[256], r2[256];
    r1[tid] = v0 + v1;
    r2[tid] = v0 * v0 + v1 * v1;
    __syncthreads();
    for (int st = 128; st > 0; st >>= 1) {
        if (tid < st) { r1[tid] += r1[tid + st]; r2[tid] += r2[tid + st]; }
        __syncthreads();
    }
    float mean = r1[0] * (1.f / DH);
    float var  = r2[0] * (1.f / DH) - mean * mean;
    float inv  = rsqrtf(var + 1e-5f);
    #pragma unroll
    for (int p = 0; p < 2; p++) {
        int i = tid + p * 256;
        int c = hh * DH + i;
        float z  = d_up[(size_t)row * 2 * INNER + INNER + c];
        float sz = z / (1.f + expf(-z));
        float hv = p ? v1 : v0;
        float val = ((hv - mean) * inv * mhw[c] + skipw[c] * d_xact[(size_t)row * INNER + c]) * sz;
        __nv_bfloat16 hi, lo;
        split1(val, hi, lo);
        d_hhi[(size_t)row * INNER + c] = hi;
        d_hlo[(size_t)row * INNER + c] = lo;
    }
}

// ---------------- final projection ----------------
__global__ void proj_kernel(const float* __restrict__ pw,
                            const float* __restrict__ pb,
                            float* __restrict__ out)
{
    int o = blockIdx.x * blockDim.x + threadIdx.x;   // 0..OUT-1
    int b = blockIdx.y;
    const float* l = d_last + (size_t)b * E;
    float acc = pb[o];
    for (int e = 0; e < E; e++) acc += l[e] * pw[(size_t)e * OUT + o];
    out[b * OUT + o] = acc;
}

// ---------------- host launcher ----------------
extern "C" void kernel_launch(void* const* d_in, const int* in_sizes, int n_in,
                              void* d_out, int out_size)
{
    const float* in_x      = (const float*)d_in[0];
    const float* ln_w      = (const float*)d_in[1];
    const float* w_up      = (const float*)d_in[2];
    const float* conv_w    = (const float*)d_in[3];
    const float* conv_b    = (const float*)d_in[4];
    const float* wq        = (const float*)d_in[5];
    const float* wk        = (const float*)d_in[6];
    const float* wv        = (const float*)d_in[7];
    const float* ig_w      = (const float*)d_in[8];
    const float* ig_b      = (const float*)d_in[9];
    const float* fg_w      = (const float*)d_in[10];
    const float* fg_b      = (const float*)d_in[11];
    const float* skip      = (const float*)d_in[12];
    const float* mhn_w     = (const float*)d_in[13];
    const float* w_down    = (const float*)d_in[14];
    const float* post_ln_w = (const float*)d_in[15];
    const float* proj_w    = (const float*)d_in[16];
    const float* proj_b    = (const float*)d_in[17];
    float* out = (float*)d_out;

    float *px, *pup, *plast;
    __nv_bfloat16 *pxh, *pxl, *phh, *phl, *puh, *pul, *pdh, *pdl;
    cudaGetSymbolAddress((void**)&px,    d_x);
    cudaGetSymbolAddress((void**)&pup,   d_up);
    cudaGetSymbolAddress((void**)&plast, d_last);
    cudaGetSymbolAddress((void**)&pxh,   d_xlnhi);
    cudaGetSymbolAddress((void**)&pxl,   d_xlnlo);
    cudaGetSymbolAddress((void**)&phh,   d_hhi);
    cudaGetSymbolAddress((void**)&phl,   d_hlo);
    cudaGetSymbolAddress((void**)&puh,   d_wuphi);
    cudaGetSymbolAddress((void**)&pul,   d_wuplo);
    cudaGetSymbolAddress((void**)&pdh,   d_wdnhi);
    cudaGetSymbolAddress((void**)&pdl,   d_wdnlo);

    cudaMemcpyAsync(px, in_x, sizeof(float) * (size_t)BS * E,
                    cudaMemcpyDeviceToDevice);

    // split weights (all blocks at once)
    {
        size_t nu = (size_t)NB * E * 2 * INNER;
        split_kernel<<<(unsigned)(nu / 4 / 256), 256>>>(w_up, puh, pul, nu);
        size_t nd = (size_t)NB * INNER * E;
        split_kernel<<<(unsigned)(nd / 4 / 256), 256>>>(w_down, pdh, pdl, nd);
    }

    for (int bi = 0; bi < NB; bi++) {
        ln_kernel<1><<<BS, 256>>>(px, E, ln_w + (size_t)bi * E,
                                  nullptr, pxh, pxl, E);

        dim3 gu(2 * INNER / 128, BS / 128);
        gemm_kernel<0><<<gu, 256>>>(pxh, pxl,
                                    puh + (size_t)bi * E * 2 * INNER,
                                    pul + (size_t)bi * E * 2 * INNER,
                                    pup, BS, 2 * INNER, E);

        conv_silu_kernel<<<dim3(INNER / 256, B), 256>>>(
            conv_w + (size_t)bi * INNER * CK, conv_b + (size_t)bi * INNER);

        headwise_kernel<<<dim3(NHQ / 128, BS / 16), 128>>>(
            wq + (size_t)bi * NHQ * 16, wk + (size_t)bi * NHQ * 16,
            wv + (size_t)bi * NHQ * 16);

        gate_kernel<<<BS, 256>>>(
            ig_w + (size_t)bi * 3 * INNER * NH, ig_b + (size_t)bi * NH,
            fg_w + (size_t)bi * 3 * INNER * NH, fg_b + (size_t)bi * NH);

        cumsum_kernel<<<1, 256>>>();

        mlstm_kernel<<<dim3(S, B * NH), 256>>>();

        mhnorm_kernel<<<dim3(BS, NH), 256>>>(
            mhn_w + (size_t)bi * INNER, skip + (size_t)bi * INNER);

        dim3 gd(E / 128, BS / 128);
        gemm_kernel<1><<<gd, 256>>>(phh, phl,
                                    pdh + (size_t)bi * INNER * E,
                                    pdl + (size_t)bi * INNER * E,
                                    px, BS, E, INNER);
    }

    ln_kernel<0><<<B, 256>>>(px + (size_t)(S - 1) * E, (size_t)S * E,
                             post_ln_w, plast, nullptr, nullptr, E);
    proj_kernel<<<dim3(OUT / 256, B), 256>>>(proj_w, proj_b, out);
}